// round 7
// baseline (speedup 1.0000x reference)
#include <cuda_runtime.h>
#include <cuda_bf16.h>
#include <cstdint>

// ---------------------------------------------------------------------------
// Problem constants
// ---------------------------------------------------------------------------
#define N_SRC0 700000
#define N_DST0 51200
#define N_DST1 5120
#define N_DST2 1024
#define N_EDGE0 768000
#define N_EDGE1 51200
#define N_EDGE2 5120
#define IN_FEATS 128
#define N_HIDDEN 256
#define N_CLASSES 47
#define OUT_ELEMS (N_DST2 * N_CLASSES)

// ---------------------------------------------------------------------------
// Scratch (__device__ globals)
// ---------------------------------------------------------------------------
__device__ __align__(16) float g_msg0[(size_t)N_DST0 * IN_FEATS];
__device__ __align__(16) float g_h1[(size_t)N_DST0 * N_HIDDEN];
__device__ __align__(16) float g_msg1[(size_t)N_DST1 * N_HIDDEN];
__device__ __align__(16) float g_h2[(size_t)N_DST1 * N_HIDDEN];
__device__ __align__(16) float g_msg2[(size_t)N_DST2 * N_HIDDEN];

// CSR scratch
__device__ int g_hist0[N_DST0], g_rs0[N_DST0], g_cur0[N_DST0];
__device__ int g_hist1[N_DST1], g_rs1[N_DST1], g_cur1[N_DST1];
__device__ int g_hist2[N_DST2], g_rs2[N_DST2], g_cur2[N_DST2];
__device__ int g_eidx0[N_EDGE0];
__device__ int g_eidx1[N_EDGE1];
__device__ int g_eidx2[N_EDGE2];

// ---------------------------------------------------------------------------
// Helpers
// ---------------------------------------------------------------------------
__device__ __forceinline__ void red_add_f32(float* addr, float v) {
    asm volatile("red.global.add.f32 [%0], %1;" :: "l"(addr), "f"(v) : "memory");
}

__device__ __forceinline__ uint32_t f2tf32(float f) {
    uint32_t u;
    asm("cvt.rna.tf32.f32 %0, %1;" : "=r"(u) : "f"(f));
    return u;
}

__device__ __forceinline__ void mma_tf32(float& c0, float& c1, float& c2, float& c3,
                                         uint32_t a0, uint32_t a1, uint32_t a2, uint32_t a3,
                                         uint32_t b0, uint32_t b1) {
    asm volatile("mma.sync.aligned.m16n8k8.row.col.f32.tf32.tf32.f32 "
                 "{%0,%1,%2,%3}, {%4,%5,%6,%7}, {%8,%9}, {%0,%1,%2,%3};"
                 : "+f"(c0), "+f"(c1), "+f"(c2), "+f"(c3)
                 : "r"(a0), "r"(a1), "r"(a2), "r"(a3), "r"(b0), "r"(b1));
}

__device__ __forceinline__ float inv_deg_i(int d) {
    return __fdividef(1.0f, fmaxf((float)d, 1.0f));
}

__device__ __forceinline__ void add4(float4& a, float4 b) {
    a.x += b.x; a.y += b.y; a.z += b.z; a.w += b.w;
}

// ---------------------------------------------------------------------------
// init: zero histograms, out = bias2 broadcast
// ---------------------------------------------------------------------------
__global__ void init_kernel(int* __restrict__ h0, int* __restrict__ h1,
                            int* __restrict__ h2, float* __restrict__ out,
                            const float* __restrict__ bias2) {
    int i = blockIdx.x * blockDim.x + threadIdx.x;
    if (i < N_DST0) { h0[i] = 0; return; }
    i -= N_DST0;
    if (i < N_DST1) { h1[i] = 0; return; }
    i -= N_DST1;
    if (i < N_DST2) { h2[i] = 0; return; }
    i -= N_DST2;
    if (i < OUT_ELEMS) out[i] = bias2[i % N_CLASSES];
}

// ---------------------------------------------------------------------------
// hist: degree histogram for all three layers in one launch
// ---------------------------------------------------------------------------
__global__ void hist_kernel(const int* __restrict__ dst0, const int* __restrict__ dst1,
                            const int* __restrict__ dst2,
                            int* __restrict__ h0, int* __restrict__ h1,
                            int* __restrict__ h2) {
    int i = blockIdx.x * blockDim.x + threadIdx.x;
    if (i < N_EDGE0) { atomicAdd(&h0[dst0[i]], 1); return; }
    i -= N_EDGE0;
    if (i < N_EDGE1) { atomicAdd(&h1[dst1[i]], 1); return; }
    i -= N_EDGE1;
    if (i < N_EDGE2) atomicAdd(&h2[dst2[i]], 1);
}

// ---------------------------------------------------------------------------
// scan: per-layer exclusive prefix sum (block b handles layer b).
// Produces row_start and a working cursor copy.
// ---------------------------------------------------------------------------
__global__ __launch_bounds__(1024)
void scan_kernel(const int* __restrict__ h0, int* __restrict__ rs0, int* __restrict__ cur0,
                 const int* __restrict__ h1, int* __restrict__ rs1, int* __restrict__ cur1,
                 const int* __restrict__ h2, int* __restrict__ rs2, int* __restrict__ cur2) {
    const int* h; int* rs; int* cur; int n;
    if (blockIdx.x == 0)      { h = h0; rs = rs0; cur = cur0; n = N_DST0; }
    else if (blockIdx.x == 1) { h = h1; rs = rs1; cur = cur1; n = N_DST1; }
    else                      { h = h2; rs = rs2; cur = cur2; n = N_DST2; }

    __shared__ int partial[1024];
    const int t = threadIdx.x;
    const int chunk = (n + 1023) / 1024;
    const int base = t * chunk;

    int s = 0;
    for (int i = 0; i < chunk; ++i)
        if (base + i < n) s += h[base + i];
    partial[t] = s;
    __syncthreads();

    // inclusive Hillis-Steele scan over 1024 partials
    for (int off = 1; off < 1024; off <<= 1) {
        int v = (t >= off) ? partial[t - off] : 0;
        __syncthreads();
        if (t >= off) partial[t] += v;
        __syncthreads();
    }

    int ex = (t == 0) ? 0 : partial[t - 1];
    for (int i = 0; i < chunk; ++i) {
        int idx = base + i;
        if (idx < n) {
            rs[idx]  = ex;
            cur[idx] = ex;
            ex += h[idx];
        }
    }
}

// ---------------------------------------------------------------------------
// scatter: build CSR edge lists for all layers in one launch
// ---------------------------------------------------------------------------
__global__ void scatter_kernel(const int* __restrict__ src0, const int* __restrict__ dst0,
                               const int* __restrict__ src1, const int* __restrict__ dst1,
                               const int* __restrict__ src2, const int* __restrict__ dst2,
                               int* __restrict__ cur0, int* __restrict__ cur1,
                               int* __restrict__ cur2,
                               int* __restrict__ e0, int* __restrict__ e1,
                               int* __restrict__ e2) {
    int i = blockIdx.x * blockDim.x + threadIdx.x;
    if (i < N_EDGE0) {
        int pos = atomicAdd(&cur0[dst0[i]], 1);
        e0[pos] = src0[i];
        return;
    }
    i -= N_EDGE0;
    if (i < N_EDGE1) {
        int pos = atomicAdd(&cur1[dst1[i]], 1);
        e1[pos] = src1[i];
        return;
    }
    i -= N_EDGE1;
    if (i < N_EDGE2) {
        int pos = atomicAdd(&cur2[dst2[i]], 1);
        e2[pos] = src2[i];
    }
}

// ---------------------------------------------------------------------------
// gather-sum: msg[dst] = sum over CSR edge list of h[src]. No atomics.
// One warp per dst node; lane owns C=F/128 float4 chunks. Unroll-4 over edges
// for MLP. STREAM picks evict-first loads for the big no-reuse layer-0 gather.
// ---------------------------------------------------------------------------
template <int F, bool STREAM>
__global__ __launch_bounds__(256)
void gather_kernel(const float* __restrict__ h,
                   const int* __restrict__ eidx,
                   const int* __restrict__ rs,
                   const int* __restrict__ hist,
                   float* __restrict__ msg,
                   int n_dst) {
    constexpr int C = F / 128;   // float4 chunks per lane (1 or 2)
    int gwarp = (blockIdx.x * blockDim.x + threadIdx.x) >> 5;
    int lane  = threadIdx.x & 31;
    if (gwarp >= n_dst) return;

    const int start = rs[gwarp];
    const int cnt   = hist[gwarp];

    float4 acc[C];
#pragma unroll
    for (int c = 0; c < C; ++c) acc[c] = make_float4(0.f, 0.f, 0.f, 0.f);

    int j = 0;
    for (; j + 4 <= cnt; j += 4) {
        int s0 = eidx[start + j + 0];
        int s1 = eidx[start + j + 1];
        int s2 = eidx[start + j + 2];
        int s3 = eidx[start + j + 3];
        const float4* r0 = reinterpret_cast<const float4*>(h + (size_t)s0 * F);
        const float4* r1 = reinterpret_cast<const float4*>(h + (size_t)s1 * F);
        const float4* r2 = reinterpret_cast<const float4*>(h + (size_t)s2 * F);
        const float4* r3 = reinterpret_cast<const float4*>(h + (size_t)s3 * F);
#pragma unroll
        for (int c = 0; c < C; ++c) {
            int off = lane + c * 32;
            float4 v0 = STREAM ? __ldcs(r0 + off) : __ldg(r0 + off);
            float4 v1 = STREAM ? __ldcs(r1 + off) : __ldg(r1 + off);
            float4 v2 = STREAM ? __ldcs(r2 + off) : __ldg(r2 + off);
            float4 v3 = STREAM ? __ldcs(r3 + off) : __ldg(r3 + off);
            add4(acc[c], v0); add4(acc[c], v1);
            add4(acc[c], v2); add4(acc[c], v3);
        }
    }
    for (; j < cnt; ++j) {
        int s = eidx[start + j];
        const float4* r = reinterpret_cast<const float4*>(h + (size_t)s * F);
#pragma unroll
        for (int c = 0; c < C; ++c) {
            float4 v = STREAM ? __ldcs(r + lane + c * 32) : __ldg(r + lane + c * 32);
            add4(acc[c], v);
        }
    }

    float4* mrow = reinterpret_cast<float4*>(msg + (size_t)gwarp * F);
#pragma unroll
    for (int c = 0; c < C; ++c) mrow[lane + c * 32] = acc[c];
}

// ---------------------------------------------------------------------------
// tf32 tensor-core dual GEMM (layers 0 and 1), full-width column tile:
//   C = A1 @ B1 + diag(1/max(deg,1)) * A2 @ B2 + bias   (+ optional ReLU)
// Requires: N == 256, M % 64 == 0, K % 32 == 0.
// ---------------------------------------------------------------------------
template <bool RELU>
__global__ __launch_bounds__(256, 2)
void gemm2_tc_kernel(const float* __restrict__ A1, const float* __restrict__ A2,
                     const int* __restrict__ hist,
                     const float* __restrict__ B1, const float* __restrict__ B2,
                     const float* __restrict__ bias, float* __restrict__ C,
                     int M, int N, int K) {
    constexpr int BM = 64, BN = 256, BK = 32;

    __shared__ uint32_t As[BM][BK + 4];
    __shared__ uint32_t Bs[BK][BN + 8];

    const int tid   = threadIdx.x;
    const int warp  = tid >> 5;
    const int lane  = tid & 31;
    const int g     = lane >> 2;
    const int t     = lane & 3;
    const int warpM = (warp & 1) * 32;
    const int warpN = (warp >> 1) * 64;
    const int rowBase = blockIdx.x * BM;

    float acc[2][8][4];
#pragma unroll
    for (int i = 0; i < 2; ++i)
#pragma unroll
        for (int j = 0; j < 8; ++j)
#pragma unroll
            for (int r = 0; r < 4; ++r) acc[i][j][r] = 0.f;

#pragma unroll
    for (int phase = 0; phase < 2; ++phase) {
        const float* __restrict__ A = phase ? A2 : A1;
        const float* __restrict__ B = phase ? B2 : B1;

        for (int k0 = 0; k0 < K; k0 += BK) {
#pragma unroll
            for (int i = 0; i < 2; ++i) {
                int idx = i * 256 + tid;
                int row = idx >> 3;
                int c4  = idx & 7;
                float4 v = *reinterpret_cast<const float4*>(
                    A + (size_t)(rowBase + row) * K + k0 + c4 * 4);
                if (phase == 1) {
                    float s = inv_deg_i(hist[rowBase + row]);
                    v.x *= s; v.y *= s; v.z *= s; v.w *= s;
                }
                uint4 u = make_uint4(f2tf32(v.x), f2tf32(v.y), f2tf32(v.z), f2tf32(v.w));
                *reinterpret_cast<uint4*>(&As[row][c4 * 4]) = u;
            }
#pragma unroll
            for (int i = 0; i < 8; ++i) {
                int idx = i * 256 + tid;
                int row = idx >> 6;
                int c4  = idx & 63;
                float4 v = *reinterpret_cast<const float4*>(
                    B + (size_t)(k0 + row) * N + c4 * 4);
                uint4 u = make_uint4(f2tf32(v.x), f2tf32(v.y), f2tf32(v.z), f2tf32(v.w));
                *reinterpret_cast<uint4*>(&Bs[row][c4 * 4]) = u;
            }
            __syncthreads();

#pragma unroll
            for (int ks = 0; ks < BK / 8; ++ks) {
                const int kb = ks * 8;
                uint32_t af[2][4];
#pragma unroll
                for (int mt = 0; mt < 2; ++mt) {
                    int m = warpM + mt * 16;
                    af[mt][0] = As[m + g][kb + t];
                    af[mt][1] = As[m + 8 + g][kb + t];
                    af[mt][2] = As[m + g][kb + 4 + t];
                    af[mt][3] = As[m + 8 + g][kb + 4 + t];
                }
                uint32_t bf[8][2];
#pragma unroll
                for (int nt = 0; nt < 8; ++nt) {
                    int n = warpN + nt * 8;
                    bf[nt][0] = Bs[kb + t][n + g];
                    bf[nt][1] = Bs[kb + 4 + t][n + g];
                }
#pragma unroll
                for (int mt = 0; mt < 2; ++mt)
#pragma unroll
                    for (int nt = 0; nt < 8; ++nt)
                        mma_tf32(acc[mt][nt][0], acc[mt][nt][1],
                                 acc[mt][nt][2], acc[mt][nt][3],
                                 af[mt][0], af[mt][1], af[mt][2], af[mt][3],
                                 bf[nt][0], bf[nt][1]);
            }
            __syncthreads();
        }
    }

#pragma unroll
    for (int mt = 0; mt < 2; ++mt) {
#pragma unroll
        for (int nt = 0; nt < 8; ++nt) {
            int c  = warpN + nt * 8 + 2 * t;
            float bx = bias[c], by = bias[c + 1];
            int r0 = rowBase + warpM + mt * 16 + g;
            float v0 = acc[mt][nt][0] + bx;
            float v1 = acc[mt][nt][1] + by;
            float v2 = acc[mt][nt][2] + bx;
            float v3 = acc[mt][nt][3] + by;
            if (RELU) {
                v0 = fmaxf(v0, 0.f); v1 = fmaxf(v1, 0.f);
                v2 = fmaxf(v2, 0.f); v3 = fmaxf(v3, 0.f);
            }
            *reinterpret_cast<float2*>(C + (size_t)r0 * N + c)       = make_float2(v0, v1);
            *reinterpret_cast<float2*>(C + (size_t)(r0 + 8) * N + c) = make_float2(v2, v3);
        }
    }
}

// ---------------------------------------------------------------------------
// Layer-2 split-K tf32 GEMM: C += A1@B1 + diag(1/deg)*A2@B2 (C holds bias).
// ---------------------------------------------------------------------------
__global__ __launch_bounds__(128)
void gemm2_tc_splitk(const float* __restrict__ A1, const float* __restrict__ A2,
                     const int* __restrict__ hist,
                     const float* __restrict__ B1, const float* __restrict__ B2,
                     float* __restrict__ C, int M, int N, int K) {
    constexpr int BM = 64, BN = 64, BK = 32;

    __shared__ uint32_t As[BM][BK + 4];
    __shared__ uint32_t Bs[BK][BN + 8];

    const int tid   = threadIdx.x;
    const int warp  = tid >> 5;
    const int lane  = tid & 31;
    const int g     = lane >> 2;
    const int t     = lane & 3;
    const int warpM = warp * 16;
    const int rowBase = blockIdx.x * BM;

    const int phase  = blockIdx.y >> 1;
    const int kBegin = (blockIdx.y & 1) * (K / 2);
    const float* __restrict__ A = phase ? A2 : A1;
    const float* __restrict__ B = phase ? B2 : B1;

    float acc[8][4];
#pragma unroll
    for (int i = 0; i < 8; ++i)
#pragma unroll
        for (int r = 0; r < 4; ++r) acc[i][r] = 0.f;

    for (int k0 = kBegin; k0 < kBegin + K / 2; k0 += BK) {
#pragma unroll
        for (int i = 0; i < 4; ++i) {
            int idx = i * 128 + tid;
            int row = idx >> 3;
            int c4  = idx & 7;
            float4 v = *reinterpret_cast<const float4*>(
                A + (size_t)(rowBase + row) * K + k0 + c4 * 4);
            if (phase == 1) {
                float s = inv_deg_i(hist[rowBase + row]);
                v.x *= s; v.y *= s; v.z *= s; v.w *= s;
            }
            uint4 u = make_uint4(f2tf32(v.x), f2tf32(v.y), f2tf32(v.z), f2tf32(v.w));
            *reinterpret_cast<uint4*>(&As[row][c4 * 4]) = u;
        }
#pragma unroll
        for (int i = 0; i < 16; ++i) {
            int idx = i * 128 + tid;
            int row = idx >> 6;
            int col = idx & 63;
            float v = (col < N) ? B[(size_t)(k0 + row) * N + col] : 0.f;
            Bs[row][col] = f2tf32(v);
        }
        __syncthreads();

#pragma unroll
        for (int ks = 0; ks < BK / 8; ++ks) {
            const int kb = ks * 8;
            uint32_t a0 = As[warpM + g][kb + t];
            uint32_t a1 = As[warpM + 8 + g][kb + t];
            uint32_t a2 = As[warpM + g][kb + 4 + t];
            uint32_t a3 = As[warpM + 8 + g][kb + 4 + t];
#pragma unroll
            for (int nt = 0; nt < 8; ++nt) {
                uint32_t b0 = Bs[kb + t][nt * 8 + g];
                uint32_t b1 = Bs[kb + 4 + t][nt * 8 + g];
                mma_tf32(acc[nt][0], acc[nt][1], acc[nt][2], acc[nt][3],
                         a0, a1, a2, a3, b0, b1);
            }
        }
        __syncthreads();
    }

    int r0 = rowBase + warpM + g;
#pragma unroll
    for (int nt = 0; nt < 8; ++nt) {
        int c = nt * 8 + 2 * t;
        if (c < N) {
            red_add_f32(C + (size_t)r0 * N + c, acc[nt][0]);
            red_add_f32(C + (size_t)(r0 + 8) * N + c, acc[nt][2]);
        }
        if (c + 1 < N) {
            red_add_f32(C + (size_t)r0 * N + c + 1, acc[nt][1]);
            red_add_f32(C + (size_t)(r0 + 8) * N + c + 1, acc[nt][3]);
        }
    }
}

// ---------------------------------------------------------------------------
// Launch
// ---------------------------------------------------------------------------
static inline int cdiv(int a, int b) { return (a + b - 1) / b; }

extern "C" void kernel_launch(void* const* d_in, const int* in_sizes, int n_in,
                              void* d_out, int out_size) {
    const float* x    = (const float*)d_in[0];
    const int*   src0 = (const int*)d_in[1];
    const int*   dst0 = (const int*)d_in[2];
    const int*   src1 = (const int*)d_in[3];
    const int*   dst1 = (const int*)d_in[4];
    const int*   src2 = (const int*)d_in[5];
    const int*   dst2 = (const int*)d_in[6];
    const float* Ws0  = (const float*)d_in[7];
    const float* Wn0  = (const float*)d_in[8];
    const float* b0   = (const float*)d_in[9];
    const float* Ws1  = (const float*)d_in[10];
    const float* Wn1  = (const float*)d_in[11];
    const float* b1   = (const float*)d_in[12];
    const float* Ws2  = (const float*)d_in[13];
    const float* Wn2  = (const float*)d_in[14];
    const float* b2   = (const float*)d_in[15];
    float* out = (float*)d_out;

    float *msg0, *h1, *msg1, *h2, *msg2;
    int *hist0, *rs0, *cur0, *hist1, *rs1, *cur1, *hist2, *rs2, *cur2;
    int *e0, *e1, *e2;
    cudaGetSymbolAddress((void**)&msg0, g_msg0);
    cudaGetSymbolAddress((void**)&h1,   g_h1);
    cudaGetSymbolAddress((void**)&msg1, g_msg1);
    cudaGetSymbolAddress((void**)&h2,   g_h2);
    cudaGetSymbolAddress((void**)&msg2, g_msg2);
    cudaGetSymbolAddress((void**)&hist0, g_hist0);
    cudaGetSymbolAddress((void**)&rs0,   g_rs0);
    cudaGetSymbolAddress((void**)&cur0,  g_cur0);
    cudaGetSymbolAddress((void**)&hist1, g_hist1);
    cudaGetSymbolAddress((void**)&rs1,   g_rs1);
    cudaGetSymbolAddress((void**)&cur1,  g_cur1);
    cudaGetSymbolAddress((void**)&hist2, g_hist2);
    cudaGetSymbolAddress((void**)&rs2,   g_rs2);
    cudaGetSymbolAddress((void**)&cur2,  g_cur2);
    cudaGetSymbolAddress((void**)&e0, g_eidx0);
    cudaGetSymbolAddress((void**)&e1, g_eidx1);
    cudaGetSymbolAddress((void**)&e2, g_eidx2);

    const int TPB = 256;
    const int N_INIT = N_DST0 + N_DST1 + N_DST2 + OUT_ELEMS;
    const int N_EDGES_ALL = N_EDGE0 + N_EDGE1 + N_EDGE2;

    // ---- CSR build (all layers) ----
    init_kernel<<<cdiv(N_INIT, TPB), TPB>>>(hist0, hist1, hist2, out, b2);
    hist_kernel<<<cdiv(N_EDGES_ALL, TPB), TPB>>>(dst0, dst1, dst2,
                                                 hist0, hist1, hist2);
    scan_kernel<<<3, 1024>>>(hist0, rs0, cur0, hist1, rs1, cur1, hist2, rs2, cur2);
    scatter_kernel<<<cdiv(N_EDGES_ALL, TPB), TPB>>>(src0, dst0, src1, dst1, src2, dst2,
                                                    cur0, cur1, cur2, e0, e1, e2);

    // ======================= Layer 0 =======================
    gather_kernel<IN_FEATS, true><<<cdiv(N_DST0 * 32, TPB), TPB>>>(
        x, e0, rs0, hist0, msg0, N_DST0);
    gemm2_tc_kernel<true><<<N_DST0 / 64, 256>>>(x, msg0, hist0, Ws0, Wn0, b0, h1,
                                                N_DST0, N_HIDDEN, IN_FEATS);

    // ======================= Layer 1 =======================
    gather_kernel<N_HIDDEN, false><<<cdiv(N_DST1 * 32, TPB), TPB>>>(
        h1, e1, rs1, hist1, msg1, N_DST1);
    gemm2_tc_kernel<true><<<N_DST1 / 64, 256>>>(h1, msg1, hist1, Ws1, Wn1, b1, h2,
                                                N_DST1, N_HIDDEN, N_HIDDEN);

    // ======================= Layer 2 =======================
    gather_kernel<N_HIDDEN, false><<<cdiv(N_DST2 * 32, TPB), TPB>>>(
        h2, e2, rs2, hist2, msg2, N_DST2);
    dim3 grid2(N_DST2 / 64, 4);
    gemm2_tc_splitk<<<grid2, 128>>>(h2, msg2, hist2, Ws2, Wn2, out,
                                    N_DST2, N_CLASSES, N_HIDDEN);

    (void)in_sizes; (void)n_in; (void)out_size;
}

// round 8
// speedup vs baseline: 1.3268x; 1.3268x over previous
#include <cuda_runtime.h>
#include <cuda_bf16.h>
#include <cstdint>

// ---------------------------------------------------------------------------
// Problem constants
// ---------------------------------------------------------------------------
#define N_SRC0 700000
#define N_DST0 51200
#define N_DST1 5120
#define N_DST2 1024
#define N_EDGE0 768000
#define N_EDGE1 51200
#define N_EDGE2 5120
#define IN_FEATS 128
#define N_HIDDEN 256
#define N_CLASSES 47

// ---------------------------------------------------------------------------
// Scratch (__device__ globals; 16B aligned for float4 / red.v4)
// ---------------------------------------------------------------------------
__device__ __align__(16) float g_msg0[(size_t)N_DST0 * IN_FEATS];
__device__ __align__(16) float g_deg0[N_DST0];
__device__ __align__(16) float g_h1[(size_t)N_DST0 * N_HIDDEN];
__device__ __align__(16) float g_msg1[(size_t)N_DST1 * N_HIDDEN];
__device__ __align__(16) float g_deg1[N_DST1];
__device__ __align__(16) float g_h2[(size_t)N_DST1 * N_HIDDEN];
__device__ __align__(16) float g_msg2[(size_t)N_DST2 * N_HIDDEN];
__device__ __align__(16) float g_deg2[N_DST2];

// ---------------------------------------------------------------------------
// Helpers
// ---------------------------------------------------------------------------
__device__ __forceinline__ void red_add_v4(float* addr, float4 v) {
    asm volatile("red.global.add.v4.f32 [%0], {%1, %2, %3, %4};"
                 :: "l"(addr), "f"(v.x), "f"(v.y), "f"(v.z), "f"(v.w)
                 : "memory");
}

__device__ __forceinline__ void red_add_f32(float* addr, float v) {
    asm volatile("red.global.add.f32 [%0], %1;" :: "l"(addr), "f"(v) : "memory");
}

__device__ __forceinline__ uint32_t f2tf32(float f) {
    uint32_t u;
    asm("cvt.rna.tf32.f32 %0, %1;" : "=r"(u) : "f"(f));
    return u;
}

__device__ __forceinline__ void mma_tf32(float& c0, float& c1, float& c2, float& c3,
                                         uint32_t a0, uint32_t a1, uint32_t a2, uint32_t a3,
                                         uint32_t b0, uint32_t b1) {
    asm volatile("mma.sync.aligned.m16n8k8.row.col.f32.tf32.tf32.f32 "
                 "{%0,%1,%2,%3}, {%4,%5,%6,%7}, {%8,%9}, {%0,%1,%2,%3};"
                 : "+f"(c0), "+f"(c1), "+f"(c2), "+f"(c3)
                 : "r"(a0), "r"(a1), "r"(a2), "r"(a3), "r"(b0), "r"(b1));
}

__device__ __forceinline__ float inv_deg(float d) {
    return __fdividef(1.0f, fmaxf(d, 1.0f));
}

// ---------------------------------------------------------------------------
// One fused init kernel: zero all msg/deg buffers; out = bias2 broadcast.
// ---------------------------------------------------------------------------
#define F4_MSG0 (N_DST0 * IN_FEATS / 4)
#define F4_DEG0 (N_DST0 / 4)
#define F4_MSG1 (N_DST1 * N_HIDDEN / 4)
#define F4_DEG1 (N_DST1 / 4)
#define F4_MSG2 (N_DST2 * N_HIDDEN / 4)
#define F4_DEG2 (N_DST2 / 4)
#define F4_TOTAL (F4_MSG0 + F4_DEG0 + F4_MSG1 + F4_DEG1 + F4_MSG2 + F4_DEG2)
#define OUT_ELEMS (N_DST2 * N_CLASSES)

__global__ void init_kernel(float4* __restrict__ msg0, float4* __restrict__ deg0,
                            float4* __restrict__ msg1, float4* __restrict__ deg1,
                            float4* __restrict__ msg2, float4* __restrict__ deg2,
                            float* __restrict__ out, const float* __restrict__ bias2) {
    int i = blockIdx.x * blockDim.x + threadIdx.x;
    float4 z = make_float4(0.f, 0.f, 0.f, 0.f);
    if (i < F4_TOTAL) {
        int j = i;
        if (j < F4_MSG0) { msg0[j] = z; return; }
        j -= F4_MSG0;
        if (j < F4_DEG0) { deg0[j] = z; return; }
        j -= F4_DEG0;
        if (j < F4_MSG1) { msg1[j] = z; return; }
        j -= F4_MSG1;
        if (j < F4_DEG1) { deg1[j] = z; return; }
        j -= F4_DEG1;
        if (j < F4_MSG2) { msg2[j] = z; return; }
        j -= F4_MSG2;
        deg2[j] = z;
        return;
    }
    int j = i - F4_TOTAL;
    if (j < OUT_ELEMS) out[j] = bias2[j % N_CLASSES];
}

// ---------------------------------------------------------------------------
// Edge aggregation, ILP=4: each thread handles FOUR float4 chunks of one
// edge's feature row (4 independent gathers + 4 REDs) -> MLP 4.
// LPE = F/16 lanes per edge; lane handles f4 slots {lane + c*LPE, c=0..3}.
// ---------------------------------------------------------------------------
template <int F>
__global__ __launch_bounds__(256)
void aggregate_kernel(const float* __restrict__ h,
                      const int* __restrict__ src,
                      const int* __restrict__ dst,
                      float* __restrict__ msg,
                      float* __restrict__ deg,
                      int n_edge) {
    constexpr int LPE = F / 16;                 // lanes per edge (8 or 16)
    int gtid = blockIdx.x * blockDim.x + threadIdx.x;
    int e    = gtid / LPE;
    int lane = gtid % LPE;
    if (e >= n_edge) return;

    int s = src[e];
    int d = dst[e];

    const float4* row = reinterpret_cast<const float4*>(h + (size_t)s * F);
    float4 v0 = __ldcs(row + lane);
    float4 v1 = __ldcs(row + lane + LPE);
    float4 v2 = __ldcs(row + lane + 2 * LPE);
    float4 v3 = __ldcs(row + lane + 3 * LPE);

    float* mrow = msg + (size_t)d * F;
    red_add_v4(mrow + (size_t)lane * 4, v0);
    red_add_v4(mrow + (size_t)(lane + LPE) * 4, v1);
    red_add_v4(mrow + (size_t)(lane + 2 * LPE) * 4, v2);
    red_add_v4(mrow + (size_t)(lane + 3 * LPE) * 4, v3);

    if (lane == 0) red_add_f32(&deg[d], 1.0f);
}

// ---------------------------------------------------------------------------
// tf32 tensor-core dual GEMM (layers 0 and 1), full-width column tile:
//   C = A1 @ B1 + diag(1/max(deg,1)) * A2 @ B2 + bias   (+ optional ReLU)
// Requires: N == 256, M % 64 == 0, K % 32 == 0.
// BM=64, BN=256, BK=32; 256 threads = 8 warps (2 along M x 4 along N),
// warp tile 32x64 = 2 m-tiles x 8 n-tiles of m16n8k8.
// ---------------------------------------------------------------------------
template <bool RELU>
__global__ __launch_bounds__(256, 2)
void gemm2_tc_kernel(const float* __restrict__ A1, const float* __restrict__ A2,
                     const float* __restrict__ deg,
                     const float* __restrict__ B1, const float* __restrict__ B2,
                     const float* __restrict__ bias, float* __restrict__ C,
                     int M, int N, int K) {
    constexpr int BM = 64, BN = 256, BK = 32;

    __shared__ uint32_t As[BM][BK + 4];
    __shared__ uint32_t Bs[BK][BN + 8];

    const int tid   = threadIdx.x;
    const int warp  = tid >> 5;
    const int lane  = tid & 31;
    const int g     = lane >> 2;
    const int t     = lane & 3;
    const int warpM = (warp & 1) * 32;
    const int warpN = (warp >> 1) * 64;
    const int rowBase = blockIdx.x * BM;

    float acc[2][8][4];
#pragma unroll
    for (int i = 0; i < 2; ++i)
#pragma unroll
        for (int j = 0; j < 8; ++j)
#pragma unroll
            for (int r = 0; r < 4; ++r) acc[i][j][r] = 0.f;

#pragma unroll
    for (int phase = 0; phase < 2; ++phase) {
        const float* __restrict__ A = phase ? A2 : A1;
        const float* __restrict__ B = phase ? B2 : B1;

        for (int k0 = 0; k0 < K; k0 += BK) {
#pragma unroll
            for (int i = 0; i < 2; ++i) {
                int idx = i * 256 + tid;
                int row = idx >> 3;
                int c4  = idx & 7;
                float4 v = *reinterpret_cast<const float4*>(
                    A + (size_t)(rowBase + row) * K + k0 + c4 * 4);
                if (phase == 1) {
                    float s = inv_deg(deg[rowBase + row]);
                    v.x *= s; v.y *= s; v.z *= s; v.w *= s;
                }
                uint4 u = make_uint4(f2tf32(v.x), f2tf32(v.y), f2tf32(v.z), f2tf32(v.w));
                *reinterpret_cast<uint4*>(&As[row][c4 * 4]) = u;
            }
#pragma unroll
            for (int i = 0; i < 8; ++i) {
                int idx = i * 256 + tid;
                int row = idx >> 6;
                int c4  = idx & 63;
                float4 v = *reinterpret_cast<const float4*>(
                    B + (size_t)(k0 + row) * N + c4 * 4);
                uint4 u = make_uint4(f2tf32(v.x), f2tf32(v.y), f2tf32(v.z), f2tf32(v.w));
                *reinterpret_cast<uint4*>(&Bs[row][c4 * 4]) = u;
            }
            __syncthreads();

#pragma unroll
            for (int ks = 0; ks < BK / 8; ++ks) {
                const int kb = ks * 8;
                uint32_t af[2][4];
#pragma unroll
                for (int mt = 0; mt < 2; ++mt) {
                    int m = warpM + mt * 16;
                    af[mt][0] = As[m + g][kb + t];
                    af[mt][1] = As[m + 8 + g][kb + t];
                    af[mt][2] = As[m + g][kb + 4 + t];
                    af[mt][3] = As[m + 8 + g][kb + 4 + t];
                }
                uint32_t bf[8][2];
#pragma unroll
                for (int nt = 0; nt < 8; ++nt) {
                    int n = warpN + nt * 8;
                    bf[nt][0] = Bs[kb + t][n + g];
                    bf[nt][1] = Bs[kb + 4 + t][n + g];
                }
#pragma unroll
                for (int mt = 0; mt < 2; ++mt)
#pragma unroll
                    for (int nt = 0; nt < 8; ++nt)
                        mma_tf32(acc[mt][nt][0], acc[mt][nt][1],
                                 acc[mt][nt][2], acc[mt][nt][3],
                                 af[mt][0], af[mt][1], af[mt][2], af[mt][3],
                                 bf[nt][0], bf[nt][1]);
            }
            __syncthreads();
        }
    }

#pragma unroll
    for (int mt = 0; mt < 2; ++mt) {
#pragma unroll
        for (int nt = 0; nt < 8; ++nt) {
            int c  = warpN + nt * 8 + 2 * t;
            float bx = bias[c], by = bias[c + 1];
            int r0 = rowBase + warpM + mt * 16 + g;
            float v0 = acc[mt][nt][0] + bx;
            float v1 = acc[mt][nt][1] + by;
            float v2 = acc[mt][nt][2] + bx;
            float v3 = acc[mt][nt][3] + by;
            if (RELU) {
                v0 = fmaxf(v0, 0.f); v1 = fmaxf(v1, 0.f);
                v2 = fmaxf(v2, 0.f); v3 = fmaxf(v3, 0.f);
            }
            *reinterpret_cast<float2*>(C + (size_t)r0 * N + c)       = make_float2(v0, v1);
            *reinterpret_cast<float2*>(C + (size_t)(r0 + 8) * N + c) = make_float2(v2, v3);
        }
    }
}

// ---------------------------------------------------------------------------
// Layer-2 split-K tf32 GEMM: C += A1@B1 + diag(1/deg)*A2@B2 (C holds bias).
// N = 47 (padded to 64 in smem). grid = (M/64, 4).
// ---------------------------------------------------------------------------
__global__ __launch_bounds__(128)
void gemm2_tc_splitk(const float* __restrict__ A1, const float* __restrict__ A2,
                     const float* __restrict__ deg,
                     const float* __restrict__ B1, const float* __restrict__ B2,
                     float* __restrict__ C, int M, int N, int K) {
    constexpr int BM = 64, BN = 64, BK = 32;

    __shared__ uint32_t As[BM][BK + 4];
    __shared__ uint32_t Bs[BK][BN + 8];

    const int tid   = threadIdx.x;
    const int warp  = tid >> 5;
    const int lane  = tid & 31;
    const int g     = lane >> 2;
    const int t     = lane & 3;
    const int warpM = warp * 16;
    const int rowBase = blockIdx.x * BM;

    const int phase  = blockIdx.y >> 1;
    const int kBegin = (blockIdx.y & 1) * (K / 2);
    const float* __restrict__ A = phase ? A2 : A1;
    const float* __restrict__ B = phase ? B2 : B1;

    float acc[8][4];
#pragma unroll
    for (int i = 0; i < 8; ++i)
#pragma unroll
        for (int r = 0; r < 4; ++r) acc[i][r] = 0.f;

    for (int k0 = kBegin; k0 < kBegin + K / 2; k0 += BK) {
#pragma unroll
        for (int i = 0; i < 4; ++i) {
            int idx = i * 128 + tid;
            int row = idx >> 3;
            int c4  = idx & 7;
            float4 v = *reinterpret_cast<const float4*>(
                A + (size_t)(rowBase + row) * K + k0 + c4 * 4);
            if (phase == 1) {
                float s = inv_deg(deg[rowBase + row]);
                v.x *= s; v.y *= s; v.z *= s; v.w *= s;
            }
            uint4 u = make_uint4(f2tf32(v.x), f2tf32(v.y), f2tf32(v.z), f2tf32(v.w));
            *reinterpret_cast<uint4*>(&As[row][c4 * 4]) = u;
        }
#pragma unroll
        for (int i = 0; i < 16; ++i) {
            int idx = i * 128 + tid;
            int row = idx >> 6;
            int col = idx & 63;
            float v = (col < N) ? B[(size_t)(k0 + row) * N + col] : 0.f;
            Bs[row][col] = f2tf32(v);
        }
        __syncthreads();

#pragma unroll
        for (int ks = 0; ks < BK / 8; ++ks) {
            const int kb = ks * 8;
            uint32_t a0 = As[warpM + g][kb + t];
            uint32_t a1 = As[warpM + 8 + g][kb + t];
            uint32_t a2 = As[warpM + g][kb + 4 + t];
            uint32_t a3 = As[warpM + 8 + g][kb + 4 + t];
#pragma unroll
            for (int nt = 0; nt < 8; ++nt) {
                uint32_t b0 = Bs[kb + t][nt * 8 + g];
                uint32_t b1 = Bs[kb + 4 + t][nt * 8 + g];
                mma_tf32(acc[nt][0], acc[nt][1], acc[nt][2], acc[nt][3],
                         a0, a1, a2, a3, b0, b1);
            }
        }
        __syncthreads();
    }

    int r0 = rowBase + warpM + g;
#pragma unroll
    for (int nt = 0; nt < 8; ++nt) {
        int c = nt * 8 + 2 * t;
        if (c < N) {
            red_add_f32(C + (size_t)r0 * N + c, acc[nt][0]);
            red_add_f32(C + (size_t)(r0 + 8) * N + c, acc[nt][2]);
        }
        if (c + 1 < N) {
            red_add_f32(C + (size_t)r0 * N + c + 1, acc[nt][1]);
            red_add_f32(C + (size_t)(r0 + 8) * N + c + 1, acc[nt][3]);
        }
    }
}

// ---------------------------------------------------------------------------
// Launch
// ---------------------------------------------------------------------------
static inline int cdiv(int a, int b) { return (a + b - 1) / b; }

extern "C" void kernel_launch(void* const* d_in, const int* in_sizes, int n_in,
                              void* d_out, int out_size) {
    const float* x    = (const float*)d_in[0];
    const int*   src0 = (const int*)d_in[1];
    const int*   dst0 = (const int*)d_in[2];
    const int*   src1 = (const int*)d_in[3];
    const int*   dst1 = (const int*)d_in[4];
    const int*   src2 = (const int*)d_in[5];
    const int*   dst2 = (const int*)d_in[6];
    const float* Ws0  = (const float*)d_in[7];
    const float* Wn0  = (const float*)d_in[8];
    const float* b0   = (const float*)d_in[9];
    const float* Ws1  = (const float*)d_in[10];
    const float* Wn1  = (const float*)d_in[11];
    const float* b1   = (const float*)d_in[12];
    const float* Ws2  = (const float*)d_in[13];
    const float* Wn2  = (const float*)d_in[14];
    const float* b2   = (const float*)d_in[15];
    float* out = (float*)d_out;

    float *msg0, *deg0, *h1, *msg1, *deg1, *h2, *msg2, *deg2;
    cudaGetSymbolAddress((void**)&msg0, g_msg0);
    cudaGetSymbolAddress((void**)&deg0, g_deg0);
    cudaGetSymbolAddress((void**)&h1,   g_h1);
    cudaGetSymbolAddress((void**)&msg1, g_msg1);
    cudaGetSymbolAddress((void**)&deg1, g_deg1);
    cudaGetSymbolAddress((void**)&h2,   g_h2);
    cudaGetSymbolAddress((void**)&msg2, g_msg2);
    cudaGetSymbolAddress((void**)&deg2, g_deg2);

    const int TPB = 256;

    // ---- one fused init: zero all msg/deg, out = bias2 ----
    init_kernel<<<cdiv(F4_TOTAL + OUT_ELEMS, TPB), TPB>>>(
        (float4*)msg0, (float4*)deg0, (float4*)msg1, (float4*)deg1,
        (float4*)msg2, (float4*)deg2, out, b2);

    // ======================= Layer 0 =======================
    {
        long long threads = (long long)N_EDGE0 * (IN_FEATS / 16);
        aggregate_kernel<IN_FEATS><<<(int)((threads + TPB - 1) / TPB), TPB>>>(
            x, src0, dst0, msg0, deg0, N_EDGE0);

        gemm2_tc_kernel<true><<<N_DST0 / 64, 256>>>(x, msg0, deg0, Ws0, Wn0, b0, h1,
                                                    N_DST0, N_HIDDEN, IN_FEATS);
    }

    // ======================= Layer 1 =======================
    {
        long long threads = (long long)N_EDGE1 * (N_HIDDEN / 16);
        aggregate_kernel<N_HIDDEN><<<(int)((threads + TPB - 1) / TPB), TPB>>>(
            h1, src1, dst1, msg1, deg1, N_EDGE1);

        gemm2_tc_kernel<true><<<N_DST1 / 64, 256>>>(h1, msg1, deg1, Ws1, Wn1, b1, h2,
                                                    N_DST1, N_HIDDEN, N_HIDDEN);
    }

    // ======================= Layer 2 =======================
    {
        long long threads = (long long)N_EDGE2 * (N_HIDDEN / 16);
        aggregate_kernel<N_HIDDEN><<<(int)((threads + TPB - 1) / TPB), TPB>>>(
            h2, src2, dst2, msg2, deg2, N_EDGE2);

        dim3 grid2(N_DST2 / 64, 4);
        gemm2_tc_splitk<<<grid2, 128>>>(h2, msg2, deg2, Ws2, Wn2, out,
                                        N_DST2, N_CLASSES, N_HIDDEN);
    }

    (void)in_sizes; (void)n_in; (void)out_size;
}